// round 2
// baseline (speedup 1.0000x reference)
#include <cuda_runtime.h>
#include <math.h>

// Problem constants
#define NN_TOK 2048
#define EDIM   1024
#define NLAYER 4

// Scratch (device globals — no allocation allowed)
__device__ float g_x[NN_TOK * EDIM];          // activations [2048,1024]
__device__ float g_qkv[NN_TOK * 3 * EDIM];    // qkv          [2048,3072]
__device__ float g_w[NN_TOK * NN_TOK];        // scores/weights [2048,2048]
__device__ float g_wv[NN_TOK * EDIM];         // w@v          [2048,1024]

// ---------------------------------------------------------------------------
// Tiled SGEMM: C[M,Nc] = alpha * A @ op(B) (+ bias)
//   BT=true : B is [Nc,K] row-major (C = A @ B^T)       -- "NT"
//   BT=false: B is [K,Nc] row-major (C = A @ B)         -- "NN"
//   CSKIP   : skip blocks strictly above the diagonal (causal scores)
//   KLIM    : limit K to (blockRow+1)*128 (w is lower-triangular)
// Block tile 128x128, K tile 16, 256 threads, 8x8 per-thread microtile.
// All dims are multiples of 128/16 so no bounds checks.
// ---------------------------------------------------------------------------
template<bool BT, bool BIAS, bool CSKIP, bool KLIM>
__global__ __launch_bounds__(256) void gemm128(
    const float* __restrict__ A, int lda,
    const float* __restrict__ B, int ldb,
    float* __restrict__ C, int ldc,
    const float* __restrict__ bias,
    int K, float alpha)
{
    const int bx = blockIdx.x, by = blockIdx.y;
    if (CSKIP && bx > by) return;
    const int Keff = KLIM ? min(K, (by + 1) * 128) : K;

    const int tid = threadIdx.x;
    const int tx = tid & 15;     // 0..15  -> column groups
    const int ty = tid >> 4;     // 0..15  -> row groups

    __shared__ float As[16][128];
    __shared__ float Bs[16][128];

    const float* Ablk = A + (size_t)by * 128 * lda;

    float acc[8][8];
#pragma unroll
    for (int i = 0; i < 8; i++)
#pragma unroll
        for (int j = 0; j < 8; j++) acc[i][j] = 0.f;

    for (int kt = 0; kt < Keff; kt += 16) {
        // Load A tile (128 x 16), store transposed As[k][m]
#pragma unroll
        for (int r = 0; r < 2; r++) {
            int i = r * 256 + tid;            // 0..511 float4s
            int row = i >> 2, c4 = i & 3;
            float4 v = *reinterpret_cast<const float4*>(
                Ablk + (size_t)row * lda + kt + c4 * 4);
            As[c4 * 4 + 0][row] = v.x;
            As[c4 * 4 + 1][row] = v.y;
            As[c4 * 4 + 2][row] = v.z;
            As[c4 * 4 + 3][row] = v.w;
        }
        if (BT) {
            const float* Bblk = B + (size_t)bx * 128 * ldb;
#pragma unroll
            for (int r = 0; r < 2; r++) {
                int i = r * 256 + tid;
                int row = i >> 2, c4 = i & 3;
                float4 v = *reinterpret_cast<const float4*>(
                    Bblk + (size_t)row * ldb + kt + c4 * 4);
                Bs[c4 * 4 + 0][row] = v.x;
                Bs[c4 * 4 + 1][row] = v.y;
                Bs[c4 * 4 + 2][row] = v.z;
                Bs[c4 * 4 + 3][row] = v.w;
            }
        } else {
            const float* Bblk = B + (size_t)kt * ldb + bx * 128;
#pragma unroll
            for (int r = 0; r < 2; r++) {
                int i = r * 256 + tid;        // 16 rows x 32 float4s
                int kk = i >> 5, n4 = i & 31;
                float4 v = *reinterpret_cast<const float4*>(
                    Bblk + (size_t)kk * ldb + n4 * 4);
                reinterpret_cast<float4*>(&Bs[kk][0])[n4] = v;
            }
        }
        __syncthreads();

#pragma unroll
        for (int kk = 0; kk < 16; kk++) {
            float a[8], b[8];
            *(float4*)&a[0] = *(const float4*)&As[kk][ty * 4];
            *(float4*)&a[4] = *(const float4*)&As[kk][64 + ty * 4];
            *(float4*)&b[0] = *(const float4*)&Bs[kk][tx * 4];
            *(float4*)&b[4] = *(const float4*)&Bs[kk][64 + tx * 4];
#pragma unroll
            for (int i = 0; i < 8; i++)
#pragma unroll
                for (int j = 0; j < 8; j++)
                    acc[i][j] = fmaf(a[i], b[j], acc[i][j]);
        }
        __syncthreads();
    }

    // Writeback (rows: ih*64 + ty*4 + i ; cols: jh*64 + tx*4 + j)
#pragma unroll
    for (int ih = 0; ih < 2; ih++)
#pragma unroll
        for (int i = 0; i < 4; i++) {
            int row = by * 128 + ih * 64 + ty * 4 + i;
#pragma unroll
            for (int jh = 0; jh < 2; jh++) {
                int col0 = bx * 128 + jh * 64 + tx * 4;
                float4 v;
                v.x = alpha * acc[ih * 4 + i][jh * 4 + 0];
                v.y = alpha * acc[ih * 4 + i][jh * 4 + 1];
                v.z = alpha * acc[ih * 4 + i][jh * 4 + 2];
                v.w = alpha * acc[ih * 4 + i][jh * 4 + 3];
                if (BIAS) {
                    v.x += bias[col0 + 0];
                    v.y += bias[col0 + 1];
                    v.z += bias[col0 + 2];
                    v.w += bias[col0 + 3];
                }
                *reinterpret_cast<float4*>(C + (size_t)row * ldc + col0) = v;
            }
        }
}

// ---------------------------------------------------------------------------
// Causal softmax over row i (valid length i+1), in-place in g_w, and
// accumulate 0.25 * w into out (store on first layer, add after).
// One block per row.
// ---------------------------------------------------------------------------
__global__ __launch_bounds__(256) void softmax_causal_acc(
    float* __restrict__ w, float* __restrict__ out, int first)
{
    const int i = blockIdx.x;
    const int len = i + 1;
    const int tid = threadIdx.x;

    __shared__ float row[NN_TOK];
    __shared__ float red[256];

    float* wr = w + (size_t)i * NN_TOK;

    float m = -3.4e38f;
    for (int j = tid; j < len; j += 256) {
        float v = wr[j];
        row[j] = v;
        m = fmaxf(m, v);
    }
    red[tid] = m;
    __syncthreads();
#pragma unroll
    for (int s = 128; s > 0; s >>= 1) {
        if (tid < s) red[tid] = fmaxf(red[tid], red[tid + s]);
        __syncthreads();
    }
    m = red[0];
    __syncthreads();

    float sum = 0.f;
    for (int j = tid; j < len; j += 256) {
        // argument is (v - max) <= 0 and finite; __expf ulp error is
        // negligible relative to the 1e-3 gate after normalization.
        float e = __expf(row[j] - m);
        row[j] = e;
        sum += e;
    }
    red[tid] = sum;
    __syncthreads();
#pragma unroll
    for (int s = 128; s > 0; s >>= 1) {
        if (tid < s) red[tid] += red[tid + s];
        __syncthreads();
    }
    const float inv = 1.0f / red[0];

    float* outr = out + (size_t)i * NN_TOK;
    for (int j = tid; j < NN_TOK; j += 256) {
        float v = (j < len) ? row[j] * inv : 0.f;
        wr[j] = v;
        if (first) outr[j] = 0.25f * v;
        else       outr[j] += 0.25f * v;
    }
}

// Copy input activations into scratch x
__global__ void copy_kernel(const float* __restrict__ src, float* __restrict__ dst, int n)
{
    int idx = blockIdx.x * blockDim.x + threadIdx.x;
    if (idx < n) dst[idx] = src[idx];
}

extern "C" void kernel_launch(void* const* d_in, const int* in_sizes, int n_in,
                              void* d_out, int out_size)
{
    const float* mentions = (const float*)d_in[0];  // [2048,1024]
    const float* Wqkv     = (const float*)d_in[1];  // [4,3072,1024]
    const float* bqkv     = (const float*)d_in[2];  // [4,3072]
    const float* Wo       = (const float*)d_in[3];  // [4,1024,1024]
    const float* bo       = (const float*)d_in[4];  // [4,1024]
    float* out            = (float*)d_out;          // [2048,2048]

    // Resolve all scratch symbols up front (stream-independent, capture-safe)
    float *x, *qkv, *w, *wv;
    cudaGetSymbolAddress((void**)&x,   g_x);
    cudaGetSymbolAddress((void**)&qkv, g_qkv);
    cudaGetSymbolAddress((void**)&w,   g_w);
    cudaGetSymbolAddress((void**)&wv,  g_wv);

    const float scale = 1.0f / 32.0f;  // 1/sqrt(1024)

    // x = mentions
    copy_kernel<<<(NN_TOK * EDIM + 255) / 256, 256>>>(mentions, x, NN_TOK * EDIM);

    for (int l = 0; l < NLAYER; l++) {
        const float* Wq = Wqkv + (size_t)l * 3 * EDIM * EDIM;
        const float* bq = bqkv + (size_t)l * 3 * EDIM;
        const float* Wl = Wo   + (size_t)l * EDIM * EDIM;
        const float* bl = bo   + (size_t)l * EDIM;

        // qkv = x @ Wqkv[l]^T + bqkv[l]   [2048,3072]
        gemm128<true, true, false, false><<<dim3(24, 16), 256>>>(
            x, EDIM, Wq, EDIM, qkv, 3 * EDIM, bq, EDIM, 1.0f);

        // scores = scale * q @ k^T (lower-triangular blocks only)  [2048,2048]
        gemm128<true, false, true, false><<<dim3(16, 16), 256>>>(
            qkv, 3 * EDIM, qkv + EDIM, 3 * EDIM, w, NN_TOK, nullptr, EDIM, scale);

        // causal softmax in-place, accumulate 0.25*w into out
        softmax_causal_acc<<<NN_TOK, 256>>>(w, out, l == 0 ? 1 : 0);

        // wv = w @ v   [2048,1024]  (k limited per block row)
        gemm128<false, false, false, true><<<dim3(8, 16), 256>>>(
            w, NN_TOK, qkv + 2 * EDIM, 3 * EDIM, wv, EDIM, nullptr, NN_TOK, 1.0f);

        // x = wv @ Wo[l]^T + bo[l]   [2048,1024]
        gemm128<true, true, false, false><<<dim3(8, 16), 256>>>(
            wv, EDIM, Wl, EDIM, x, EDIM, bl, EDIM, 1.0f);
    }
}

// round 4
// speedup vs baseline: 2.2052x; 2.2052x over previous
#include <cuda_runtime.h>
#include <cuda_bf16.h>
#include <stdint.h>
#include <math.h>

#define NTOK 2048
#define EDIM 1024
#define NLAYER 4

// ---------------------------------------------------------------------------
// Scratch (device globals — allocation is forbidden)
// ---------------------------------------------------------------------------
__device__ __nv_bfloat16 g_xhi[NTOK * EDIM], g_xlo[NTOK * EDIM];
__device__ __nv_bfloat16 g_qkvhi[NTOK * 3 * EDIM], g_qkvlo[NTOK * 3 * EDIM];
__device__ float         g_w[NTOK * NTOK];
__device__ __nv_bfloat16 g_whi[NTOK * NTOK], g_wlo[NTOK * NTOK];
__device__ __nv_bfloat16 g_vThi[EDIM * NTOK], g_vTlo[EDIM * NTOK];
__device__ __nv_bfloat16 g_wvhi[NTOK * EDIM], g_wvlo[NTOK * EDIM];
__device__ __nv_bfloat16 g_Wqkvhi[NLAYER * 3 * EDIM * EDIM], g_Wqkvlo[NLAYER * 3 * EDIM * EDIM];
__device__ __nv_bfloat16 g_Wohi[NLAYER * EDIM * EDIM], g_Wolo[NLAYER * EDIM * EDIM];

// ---------------------------------------------------------------------------
// Helpers
// ---------------------------------------------------------------------------
__device__ __forceinline__ uint32_t s2u(const void* p) {
    uint32_t a;
    asm("{ .reg .u64 t; cvta.to.shared.u64 t, %1; cvt.u32.u64 %0, t; }" : "=r"(a) : "l"(p));
    return a;
}
#define CPA(sm, gp) \
    asm volatile("cp.async.cg.shared.global [%0], [%1], 16;" :: "r"(sm), "l"(gp))
#define CPA_COMMIT() asm volatile("cp.async.commit_group;")
#define CPA_WAIT1()  asm volatile("cp.async.wait_group 1;")
#define CPA_WAIT0()  asm volatile("cp.async.wait_group 0;")

#define LDSM4(r0, r1, r2, r3, addr)                                          \
    asm volatile("ldmatrix.sync.aligned.m8n8.x4.shared.b16 {%0,%1,%2,%3}, [%4];" \
                 : "=r"(r0), "=r"(r1), "=r"(r2), "=r"(r3) : "r"(addr))

__device__ __forceinline__ void mma16816(float* c, const uint32_t* a, const uint32_t* b) {
    asm volatile(
        "mma.sync.aligned.m16n8k16.row.col.f32.bf16.bf16.f32 "
        "{%0,%1,%2,%3}, {%4,%5,%6,%7}, {%8,%9}, {%0,%1,%2,%3};"
        : "+f"(c[0]), "+f"(c[1]), "+f"(c[2]), "+f"(c[3])
        : "r"(a[0]), "r"(a[1]), "r"(a[2]), "r"(a[3]), "r"(b[0]), "r"(b[1]));
}

__device__ __forceinline__ uint32_t pack2bf(float a, float b) {
    __nv_bfloat162 t = __floats2bfloat162_rn(a, b);
    return *reinterpret_cast<uint32_t*>(&t);
}

// SMEM geometry: per chunk, 4 tiles of 128 rows x 32 bf16, padded to 80 B/row
// (80B pitch => conflict-free ldmatrix). Tile = 10240 B. Buffer = 4 tiles.
#define TILE_B   10240
#define BUF_B    40960
#define SMEM_BYTES (2 * BUF_B)   // 81920

// ---------------------------------------------------------------------------
// Tensor-core NT GEMM with fused 3-pass bf16 hi/lo split:
//   C[by*128.., bx*128..] = sum_k Ahi*Bhi + Ahi*Blo + Alo*Bhi
//   EPI 0: C fp32 = alpha * acc              (scores)
//   EPI 1: C bf16 hi/lo = acc                (wv)
//   EPI 2: C bf16 hi/lo = acc + bias[col]    (qkv / out-proj)
//   CSKIP: skip blocks strictly above diagonal;  KLIM: Keff = (by+1)*128
// ---------------------------------------------------------------------------
template<int EPI, bool CSKIP, bool KLIM>
__global__ void __launch_bounds__(256) gemm_mma(
    const __nv_bfloat16* __restrict__ Ahi, const __nv_bfloat16* __restrict__ Alo, int lda,
    const __nv_bfloat16* __restrict__ Bhi, const __nv_bfloat16* __restrict__ Blo, int ldb,
    float* __restrict__ Cf,
    __nv_bfloat16* __restrict__ Chi, __nv_bfloat16* __restrict__ Clo, int ldc,
    const float* __restrict__ bias, int K, float alpha)
{
    const int bx = blockIdx.x, by = blockIdx.y;
    if (CSKIP && bx > by) return;
    const int Keff = KLIM ? min(K, (by + 1) * 128) : K;
    const int nch  = Keff / 32;

    extern __shared__ __align__(128) char smem[];
    const uint32_t sb = s2u(smem);

    const int tid  = threadIdx.x;
    const int wid  = tid >> 5, lane = tid & 31;
    const int wm   = (wid & 1) * 64;     // warp m offset (2 warps)
    const int wn   = (wid >> 1) * 32;    // warp n offset (4 warps)

    // Block-level gmem bases
    const __nv_bfloat16* Abh = Ahi + (size_t)(by * 128) * lda;
    const __nv_bfloat16* Abl = Alo + (size_t)(by * 128) * lda;
    const __nv_bfloat16* Bbh = Bhi + (size_t)(bx * 128) * ldb;
    const __nv_bfloat16* Bbl = Blo + (size_t)(bx * 128) * ldb;

    // Loader indices: 512 16B vectors per tile; 2 per thread per tile
    const int v0   = tid * 2;
    const int lrow = v0 >> 2;            // shared by both vectors? no: recompute
    (void)lrow;

    // ldmatrix per-lane address components
    const uint32_t a_row = lane & 15;
    const uint32_t a_k   = (lane >> 4) * 16;
    const uint32_t b_row = (lane & 7) + (lane >> 4) * 8;
    const uint32_t b_k   = ((lane >> 3) & 1) * 16;

    float acc[4][4][4];
#pragma unroll
    for (int i = 0; i < 4; i++)
#pragma unroll
        for (int j = 0; j < 4; j++)
#pragma unroll
            for (int r = 0; r < 4; r++) acc[i][j][r] = 0.f;

    // ---- chunk loader (cp.async, 4 tiles) ----
    auto load_chunk = [&](uint32_t sbuf, int kt) {
#pragma unroll
        for (int i = 0; i < 2; i++) {
            int v = tid * 2 + i;
            int row = v >> 2, c = v & 3;
            uint32_t so = (uint32_t)row * 80 + c * 16;
            size_t ga = (size_t)row * lda + kt + c * 8;
            size_t gb = (size_t)row * ldb + kt + c * 8;
            CPA(sb + sbuf + so,              Abh + ga);
            CPA(sb + sbuf + TILE_B + so,     Abl + ga);
            CPA(sb + sbuf + 2 * TILE_B + so, Bbh + gb);
            CPA(sb + sbuf + 3 * TILE_B + so, Bbl + gb);
        }
    };

    load_chunk(0, 0);
    CPA_COMMIT();

    for (int c = 0; c < nch; c++) {
        const uint32_t buf = (c & 1) ? BUF_B : 0;
        if (c + 1 < nch) {
            load_chunk(buf ^ BUF_B, (c + 1) * 32);
            CPA_COMMIT();
            CPA_WAIT1();
        } else {
            CPA_WAIT0();
        }
        __syncthreads();

#pragma unroll
        for (int k16 = 0; k16 < 2; k16++) {
            uint32_t bh[8], bl[8];
            {
                uint32_t bb = sb + buf + 2 * TILE_B
                            + (wn + b_row) * 80 + k16 * 32 + b_k;
                LDSM4(bh[0], bh[1], bh[2], bh[3], bb);
                LDSM4(bh[4], bh[5], bh[6], bh[7], bb + 16 * 80);
                LDSM4(bl[0], bl[1], bl[2], bl[3], bb + TILE_B);
                LDSM4(bl[4], bl[5], bl[6], bl[7], bb + TILE_B + 16 * 80);
            }
#pragma unroll
            for (int mf = 0; mf < 4; mf++) {
                uint32_t ah[4], al[4];
                uint32_t ab = sb + buf
                            + (wm + mf * 16 + a_row) * 80 + k16 * 32 + a_k;
                LDSM4(ah[0], ah[1], ah[2], ah[3], ab);
                LDSM4(al[0], al[1], al[2], al[3], ab + TILE_B);
#pragma unroll
                for (int nf = 0; nf < 4; nf++) {
                    mma16816(acc[mf][nf], ah, bh + nf * 2);   // hi*hi
                    mma16816(acc[mf][nf], ah, bl + nf * 2);   // hi*lo
                    mma16816(acc[mf][nf], al, bh + nf * 2);   // lo*hi
                }
            }
        }
        __syncthreads();
    }

    // ---- epilogue ----
#pragma unroll
    for (int mf = 0; mf < 4; mf++) {
#pragma unroll
        for (int nf = 0; nf < 4; nf++) {
            const float* cc = acc[mf][nf];
            int row0 = by * 128 + wm + mf * 16 + (lane >> 2);
            int col  = bx * 128 + wn + nf * 8 + (lane & 3) * 2;
            if (EPI == 0) {
                float2 v0 = make_float2(alpha * cc[0], alpha * cc[1]);
                float2 v1 = make_float2(alpha * cc[2], alpha * cc[3]);
                *(float2*)(Cf + (size_t)row0 * ldc + col) = v0;
                *(float2*)(Cf + (size_t)(row0 + 8) * ldc + col) = v1;
            } else {
                float b0 = 0.f, b1 = 0.f;
                if (EPI == 2) { b0 = bias[col]; b1 = bias[col + 1]; }
                float v0 = cc[0] + b0, v1 = cc[1] + b1;
                float v2 = cc[2] + b0, v3 = cc[3] + b1;
                float h0 = __bfloat162float(__float2bfloat16_rn(v0));
                float h1 = __bfloat162float(__float2bfloat16_rn(v1));
                float h2 = __bfloat162float(__float2bfloat16_rn(v2));
                float h3 = __bfloat162float(__float2bfloat16_rn(v3));
                size_t o0 = (size_t)row0 * ldc + col;
                size_t o1 = (size_t)(row0 + 8) * ldc + col;
                *(uint32_t*)(Chi + o0) = pack2bf(h0, h1);
                *(uint32_t*)(Clo + o0) = pack2bf(v0 - h0, v1 - h1);
                *(uint32_t*)(Chi + o1) = pack2bf(h2, h3);
                *(uint32_t*)(Clo + o1) = pack2bf(v2 - h2, v3 - h3);
            }
        }
    }
}

// ---------------------------------------------------------------------------
// Causal softmax over row i (len = i+1) from fp32 scores; writes bf16 hi/lo
// weights (zero-padded) and accumulates 0.25*w into out.
// ---------------------------------------------------------------------------
__global__ __launch_bounds__(256) void softmax_causal_acc(
    const float* __restrict__ w,
    __nv_bfloat16* __restrict__ whi, __nv_bfloat16* __restrict__ wlo,
    float* __restrict__ out, int first)
{
    const int i = blockIdx.x;
    const int len = i + 1;
    const int tid = threadIdx.x;

    __shared__ float row[NTOK];
    __shared__ float red[256];

    const float* wr = w + (size_t)i * NTOK;

    float m = -3.4e38f;
    for (int j = tid; j < len; j += 256) {
        float v = wr[j];
        row[j] = v;
        m = fmaxf(m, v);
    }
    red[tid] = m;
    __syncthreads();
#pragma unroll
    for (int s = 128; s > 0; s >>= 1) {
        if (tid < s) red[tid] = fmaxf(red[tid], red[tid + s]);
        __syncthreads();
    }
    m = red[0];
    __syncthreads();

    float sum = 0.f;
    for (int j = tid; j < len; j += 256) {
        float e = __expf(row[j] - m);   // arg <= 0, bounded
        row[j] = e;
        sum += e;
    }
    red[tid] = sum;
    __syncthreads();
#pragma unroll
    for (int s = 128; s > 0; s >>= 1) {
        if (tid < s) red[tid] += red[tid + s];
        __syncthreads();
    }
    const float inv = 1.0f / red[0];

    float* outr = out + (size_t)i * NTOK;
    __nv_bfloat16* hr = whi + (size_t)i * NTOK;
    __nv_bfloat16* lr = wlo + (size_t)i * NTOK;
    for (int j = tid; j < NTOK; j += 256) {
        float v = (j < len) ? row[j] * inv : 0.f;
        float h = __bfloat162float(__float2bfloat16_rn(v));
        hr[j] = __float2bfloat16_rn(v);
        lr[j] = __float2bfloat16_rn(v - h);
        if (first) outr[j] = 0.25f * v;
        else       outr[j] += 0.25f * v;
    }
}

// ---------------------------------------------------------------------------
// Transpose v slice of qkv (hi & lo):  vT[c, r] = qkv[r, 2E + c]
// ---------------------------------------------------------------------------
__global__ void transpose_v(const __nv_bfloat16* __restrict__ qh,
                            const __nv_bfloat16* __restrict__ ql,
                            __nv_bfloat16* __restrict__ th,
                            __nv_bfloat16* __restrict__ tl)
{
    __shared__ __nv_bfloat16 sh[32][33];
    __shared__ __nv_bfloat16 sl[32][33];
    const int c0 = blockIdx.x * 32, r0 = blockIdx.y * 32;
    const int tx = threadIdx.x, ty = threadIdx.y;
#pragma unroll
    for (int k = 0; k < 4; k++) {
        int r = ty + k * 8;
        size_t src = (size_t)(r0 + r) * (3 * EDIM) + 2 * EDIM + c0 + tx;
        sh[r][tx] = qh[src];
        sl[r][tx] = ql[src];
    }
    __syncthreads();
#pragma unroll
    for (int k = 0; k < 4; k++) {
        int cc = ty + k * 8;
        size_t dst = (size_t)(c0 + cc) * NTOK + r0 + tx;
        th[dst] = sh[tx][cc];
        tl[dst] = sl[tx][cc];
    }
}

// fp32 -> bf16 hi/lo split (vectorized by 4)
__global__ void split_bf16(const float* __restrict__ src,
                           __nv_bfloat16* __restrict__ hi,
                           __nv_bfloat16* __restrict__ lo, int n4)
{
    int idx = blockIdx.x * blockDim.x + threadIdx.x;
    if (idx >= n4) return;
    float4 v = ((const float4*)src)[idx];
    float h0 = __bfloat162float(__float2bfloat16_rn(v.x));
    float h1 = __bfloat162float(__float2bfloat16_rn(v.y));
    float h2 = __bfloat162float(__float2bfloat16_rn(v.z));
    float h3 = __bfloat162float(__float2bfloat16_rn(v.w));
    uint2 ph, pl;
    ph.x = pack2bf(h0, h1);             ph.y = pack2bf(h2, h3);
    pl.x = pack2bf(v.x - h0, v.y - h1); pl.y = pack2bf(v.z - h2, v.w - h3);
    ((uint2*)hi)[idx] = ph;
    ((uint2*)lo)[idx] = pl;
}

// ---------------------------------------------------------------------------
extern "C" void kernel_launch(void* const* d_in, const int* in_sizes, int n_in,
                              void* d_out, int out_size)
{
    const float* mentions = (const float*)d_in[0];  // [2048,1024]
    const float* Wqkv     = (const float*)d_in[1];  // [4,3072,1024]
    const float* bqkv     = (const float*)d_in[2];  // [4,3072]
    const float* Wo       = (const float*)d_in[3];  // [4,1024,1024]
    const float* bo       = (const float*)d_in[4];  // [4,1024]
    float* out            = (float*)d_out;          // [2048,2048]

    __nv_bfloat16 *xhi, *xlo, *qkvhi, *qkvlo, *whi, *wlo, *vThi, *vTlo,
                  *wvhi, *wvlo, *Wqhi, *Wqlo, *Wohi, *Wolo;
    float* w;
    cudaGetSymbolAddress((void**)&xhi, g_xhi);     cudaGetSymbolAddress((void**)&xlo, g_xlo);
    cudaGetSymbolAddress((void**)&qkvhi, g_qkvhi); cudaGetSymbolAddress((void**)&qkvlo, g_qkvlo);
    cudaGetSymbolAddress((void**)&w, g_w);
    cudaGetSymbolAddress((void**)&whi, g_whi);     cudaGetSymbolAddress((void**)&wlo, g_wlo);
    cudaGetSymbolAddress((void**)&vThi, g_vThi);   cudaGetSymbolAddress((void**)&vTlo, g_vTlo);
    cudaGetSymbolAddress((void**)&wvhi, g_wvhi);   cudaGetSymbolAddress((void**)&wvlo, g_wvlo);
    cudaGetSymbolAddress((void**)&Wqhi, g_Wqkvhi); cudaGetSymbolAddress((void**)&Wqlo, g_Wqkvlo);
    cudaGetSymbolAddress((void**)&Wohi, g_Wohi);   cudaGetSymbolAddress((void**)&Wolo, g_Wolo);

    cudaFuncSetAttribute(gemm_mma<2, false, false>,
                         cudaFuncAttributeMaxDynamicSharedMemorySize, SMEM_BYTES);
    cudaFuncSetAttribute(gemm_mma<0, true, false>,
                         cudaFuncAttributeMaxDynamicSharedMemorySize, SMEM_BYTES);
    cudaFuncSetAttribute(gemm_mma<1, false, true>,
                         cudaFuncAttributeMaxDynamicSharedMemorySize, SMEM_BYTES);

    const float scale = 1.0f / 32.0f;   // 1/sqrt(1024)

    // Split weights + input activations into bf16 hi/lo
    {
        int n4 = NLAYER * 3 * EDIM * EDIM / 4;
        split_bf16<<<(n4 + 255) / 256, 256>>>(Wqkv, Wqhi, Wqlo, n4);
        n4 = NLAYER * EDIM * EDIM / 4;
        split_bf16<<<(n4 + 255) / 256, 256>>>(Wo, Wohi, Wolo, n4);
        n4 = NTOK * EDIM / 4;
        split_bf16<<<(n4 + 255) / 256, 256>>>(mentions, xhi, xlo, n4);
    }

    for (int l = 0; l < NLAYER; l++) {
        const __nv_bfloat16* Wqh = Wqhi + (size_t)l * 3 * EDIM * EDIM;
        const __nv_bfloat16* Wql = Wqlo + (size_t)l * 3 * EDIM * EDIM;
        const __nv_bfloat16* Woh = Wohi + (size_t)l * EDIM * EDIM;
        const __nv_bfloat16* Wol = Wolo + (size_t)l * EDIM * EDIM;
        const float* bq = bqkv + (size_t)l * 3 * EDIM;
        const float* bl = bo   + (size_t)l * EDIM;

        // qkv = x @ Wqkv^T + bqkv      -> bf16 hi/lo [2048,3072]
        gemm_mma<2, false, false><<<dim3(24, 16), 256, SMEM_BYTES>>>(
            xhi, xlo, EDIM, Wqh, Wql, EDIM,
            nullptr, qkvhi, qkvlo, 3 * EDIM, bq, EDIM, 1.0f);

        // scores = scale * q @ k^T     -> fp32 [2048,2048], lower blocks only
        gemm_mma<0, true, false><<<dim3(16, 16), 256, SMEM_BYTES>>>(
            qkvhi, qkvlo, 3 * EDIM, qkvhi + EDIM, qkvlo + EDIM, 3 * EDIM,
            w, nullptr, nullptr, NTOK, nullptr, EDIM, scale);

        // softmax -> w hi/lo, accumulate 0.25*w into out
        softmax_causal_acc<<<NTOK, 256>>>(w, whi, wlo, out, l == 0 ? 1 : 0);

        // vT = transpose of v slice
        transpose_v<<<dim3(EDIM / 32, NTOK / 32), dim3(32, 8)>>>(qkvhi, qkvlo, vThi, vTlo);

        // wv = w @ v                    -> bf16 hi/lo [2048,1024]  (K limited)
        gemm_mma<1, false, true><<<dim3(8, 16), 256, SMEM_BYTES>>>(
            whi, wlo, NTOK, vThi, vTlo, NTOK,
            nullptr, wvhi, wvlo, EDIM, nullptr, NTOK, 1.0f);

        // x = wv @ Wo^T + bo            -> bf16 hi/lo [2048,1024]
        gemm_mma<2, false, false><<<dim3(8, 16), 256, SMEM_BYTES>>>(
            wvhi, wvlo, EDIM, Woh, Wol, EDIM,
            nullptr, xhi, xlo, EDIM, bl, EDIM, 1.0f);
    }
}